// round 2
// baseline (speedup 1.0000x reference)
#include <cuda_runtime.h>
#include <math.h>

// ---------------- problem constants ----------------
#define NTOT   102400          // B*T*NODES
#define ETOT   1638400         // edges
#define BATCH  8
#define TSTEPS 32
#define NODES  400
#define NSEQ   (BATCH*NODES)   // 3200
#define D_IN   64
#define L1F    96
#define L2F    64
#define GATES  256             // 4*64
#define FC1F   128
#define FC2F   3

// ---------------- device scratch (static: allowed) ----------------
__device__ float g_colsum[64];
__device__ float g_colsumsq[64];
__device__ float g_mean[64];
__device__ float g_rstd[64];
__device__ int   g_counts[NTOT];
__device__ int   g_rowptr[NTOT + 1];
__device__ int   g_cursor[NTOT];
__device__ int   g_bsums[128];
__device__ float g_deg[NTOT];
__device__ float g_dis[NTOT];
__device__ int   g_csrsrc[ETOT];
__device__ float g_csrw[ETOT];
__device__ float g_h1pre[(size_t)NTOT * L1F];
__device__ float g_h1   [(size_t)NTOT * L1F];
__device__ float g_h2pre[(size_t)NTOT * L2F];
__device__ float g_h2   [(size_t)NTOT * L2F];
__device__ float g_xg   [(size_t)NTOT * GATES];
__device__ float g_hfin [(size_t)NSEQ * L2F];

// ---------------- init ----------------
__global__ void init_kernel() {
    int gid = blockIdx.x * blockDim.x + threadIdx.x;
    if (gid < NTOT) { g_counts[gid] = 0; g_deg[gid] = 1.0f; }
    if (gid < 64)   { g_colsum[gid] = 0.f; g_colsumsq[gid] = 0.f; }
}

// ---------------- column stats (mean/std, ddof=1) ----------------
__global__ void col_stats_kernel(const float* __restrict__ x) {
    __shared__ float ssum[256], ssq[256];
    int c  = threadIdx.x & 63;
    int rr = threadIdx.x >> 6;
    float s = 0.f, q = 0.f;
    for (int row = blockIdx.x * 4 + rr; row < NTOT; row += gridDim.x * 4) {
        float v = x[(size_t)row * 64 + c];
        s += v; q += v * v;
    }
    ssum[threadIdx.x] = s; ssq[threadIdx.x] = q;
    __syncthreads();
    if (threadIdx.x < 64) {
        float S = ssum[threadIdx.x] + ssum[threadIdx.x + 64] + ssum[threadIdx.x + 128] + ssum[threadIdx.x + 192];
        float Q = ssq [threadIdx.x] + ssq [threadIdx.x + 64] + ssq [threadIdx.x + 128] + ssq [threadIdx.x + 192];
        atomicAdd(&g_colsum[threadIdx.x], S);
        atomicAdd(&g_colsumsq[threadIdx.x], Q);
    }
}

__global__ void stats_finalize_kernel() {
    int c = threadIdx.x;
    if (c < 64) {
        float n = (float)NTOT;
        float mean = g_colsum[c] / n;
        float var  = (g_colsumsq[c] - n * mean * mean) / (n - 1.0f);
        g_mean[c] = mean;
        g_rstd[c] = rsqrtf(var);
    }
}

// ---------------- edge pass 1: histogram + weighted degree ----------------
__global__ void edge_pass1_kernel(const int* __restrict__ ei, const float* __restrict__ ea) {
    int e = blockIdx.x * blockDim.x + threadIdx.x;
    if (e >= ETOT) return;
    int dst = ei[ETOT + e];
    float w = fabsf(ea[2 * e]);
    atomicAdd(&g_counts[dst], 1);
    atomicAdd(&g_deg[dst], w);
}

// ---------------- scan (exclusive) over counts ----------------
__global__ void scan1_kernel() {
    __shared__ int tmp[1024];
    int gid = blockIdx.x * 1024 + threadIdx.x;
    int v = g_counts[gid];
    tmp[threadIdx.x] = v;
    __syncthreads();
    int val = v;
    for (int off = 1; off < 1024; off <<= 1) {
        int add = (threadIdx.x >= off) ? tmp[threadIdx.x - off] : 0;
        __syncthreads();
        val += add;
        tmp[threadIdx.x] = val;
        __syncthreads();
    }
    g_rowptr[gid] = val - v;           // exclusive, local to block
    if (threadIdx.x == 1023) g_bsums[blockIdx.x] = val;
}

__global__ void scan2_kernel() {
    if (threadIdx.x == 0 && blockIdx.x == 0) {
        int acc = 0;
        for (int i = 0; i < NTOT / 1024; i++) {
            int v = g_bsums[i];
            g_bsums[i] = acc;
            acc += v;
        }
    }
}

__global__ void scan3_kernel() {
    int gid = blockIdx.x * blockDim.x + threadIdx.x;
    if (gid >= NTOT) return;
    int rp = g_rowptr[gid] + g_bsums[gid >> 10];
    g_rowptr[gid] = rp;
    g_cursor[gid] = rp;
    g_dis[gid] = rsqrtf(g_deg[gid]);   // deg >= 1 always (self loop weight 1)
    if (gid == 0) g_rowptr[NTOT] = ETOT;
}

// ---------------- edge pass 2: scatter into CSR ----------------
__global__ void edge_scatter_kernel(const int* __restrict__ ei, const float* __restrict__ ea) {
    int e = blockIdx.x * blockDim.x + threadIdx.x;
    if (e >= ETOT) return;
    int dst = ei[ETOT + e];
    int src = ei[e];
    float w = fabsf(ea[2 * e]);
    int pos = atomicAdd(&g_cursor[dst], 1);
    g_csrsrc[pos] = src;
    g_csrw[pos] = w;
}

// ---------------- generic tiled SGEMM: C[M,Nout] = A[M,K] * B + bias (+bias2) ----------------
// BM=64, BN=64, BK=16, 256 threads (16x16), thread tile 4x4
template<bool NORM, bool TRANSB>
__global__ void gemm_kernel(const float* __restrict__ A, const float* __restrict__ Bm,
                            const float* __restrict__ bias, const float* __restrict__ bias2,
                            float* __restrict__ C, int K, int Nout) {
    __shared__ float As[16][65];
    __shared__ float Bs[16][68];
    int tid = threadIdx.x;
    int tx = tid & 15, ty = tid >> 4;
    int m0 = blockIdx.x * 64, n0 = blockIdx.y * 64;
    float acc[4][4] = {};
    for (int k0 = 0; k0 < K; k0 += 16) {
        #pragma unroll
        for (int i = 0; i < 4; i++) {
            int idx = i * 256 + tid;
            int r = idx >> 4, c = idx & 15;
            float a = A[(size_t)(m0 + r) * K + (k0 + c)];
            if (NORM) a = (a - g_mean[k0 + c]) * g_rstd[k0 + c];
            As[c][r] = a;
        }
        #pragma unroll
        for (int i = 0; i < 4; i++) {
            int idx = i * 256 + tid;
            int r = idx >> 6, c = idx & 63;
            int n = n0 + c, kk = k0 + r;
            float b = 0.f;
            if (n < Nout) b = TRANSB ? Bm[(size_t)n * K + kk] : Bm[(size_t)kk * Nout + n];
            Bs[r][c] = b;
        }
        __syncthreads();
        #pragma unroll
        for (int kk = 0; kk < 16; kk++) {
            float a[4], b[4];
            #pragma unroll
            for (int i = 0; i < 4; i++) a[i] = As[kk][ty * 4 + i];
            #pragma unroll
            for (int j = 0; j < 4; j++) b[j] = Bs[kk][tx * 4 + j];
            #pragma unroll
            for (int i = 0; i < 4; i++)
                #pragma unroll
                for (int j = 0; j < 4; j++)
                    acc[i][j] += a[i] * b[j];
        }
        __syncthreads();
    }
    #pragma unroll
    for (int i = 0; i < 4; i++) {
        int m = m0 + ty * 4 + i;
        #pragma unroll
        for (int j = 0; j < 4; j++) {
            int n = n0 + tx * 4 + j;
            if (n < Nout) {
                float v = acc[i][j];
                if (bias)  v += bias[n];
                if (bias2) v += bias2[n];
                C[(size_t)m * Nout + n] = v;
            }
        }
    }
}

// ---------------- GCN aggregation: one warp per destination node ----------------
template<int F>
__global__ void agg_kernel(const float* __restrict__ hpre, const float* __restrict__ bias,
                           float* __restrict__ out) {
    int warpId = (blockIdx.x * blockDim.x + threadIdx.x) >> 5;
    int lane = threadIdx.x & 31;
    if (warpId >= NTOT) return;
    const int R = F / 32;
    int i = warpId;
    int beg = g_rowptr[i], end = g_rowptr[i + 1];
    float di = g_dis[i];
    float acc[R];
    #pragma unroll
    for (int r = 0; r < R; r++) acc[r] = 0.f;

    for (int e0 = beg; e0 < end; e0 += 32) {
        int cnt = min(32, end - e0);
        int s = 0; float w = 0.f;
        if (lane < cnt) {
            s = g_csrsrc[e0 + lane];
            w = g_csrw[e0 + lane] * g_dis[s];
        }
        for (int j = 0; j < cnt; j++) {
            int   ss = __shfl_sync(0xffffffff, s, j);
            float ww = __shfl_sync(0xffffffff, w, j);
            const float* row = hpre + (size_t)ss * F;
            #pragma unroll
            for (int r = 0; r < R; r++)
                acc[r] += row[lane + 32 * r] * ww;
        }
    }
    const float* self = hpre + (size_t)i * F;
    #pragma unroll
    for (int r = 0; r < R; r++) {
        float v = acc[r] * di + self[lane + 32 * r] * di * di + bias[lane + 32 * r];
        out[(size_t)i * F + lane + 32 * r] = fmaxf(v, 0.f);
    }
}

// ---------------- LSTM: 4 sequences / block, thread j owns hidden unit j ----------------
__device__ __forceinline__ float sigm(float x) { return 1.0f / (1.0f + expf(-x)); }

__global__ void lstm_kernel(const float* __restrict__ xg, const float* __restrict__ w_hh,
                            float* __restrict__ hfinal) {
    extern __shared__ float sm[];
    float4* w4 = (float4*)sm;          // [k*64 + j] = {w_hh[j,k], w_hh[64+j,k], w_hh[128+j,k], w_hh[192+j,k]}
    float* h_sm = sm + 16384;          // [4][64]
    int tid = threadIdx.x;

    for (int idx = tid; idx < 4096; idx += 256) {
        int k = idx >> 6, j = idx & 63;
        w4[idx] = make_float4(w_hh[(size_t)j * 64 + k],
                              w_hh[(size_t)(64 + j) * 64 + k],
                              w_hh[(size_t)(128 + j) * 64 + k],
                              w_hh[(size_t)(192 + j) * 64 + k]);
    }
    int sl = tid >> 6;         // seq within block
    int j  = tid & 63;         // hidden unit
    int seq = blockIdx.x * 4 + sl;
    int b = seq / NODES, node = seq % NODES;
    float h = 0.f, c = 0.f;
    h_sm[sl * 64 + j] = 0.f;
    __syncthreads();

    for (int t = 0; t < TSTEPS; t++) {
        size_t row = ((size_t)(b * TSTEPS + t) * NODES + node) * GATES;
        float gi = xg[row + j];
        float gf = xg[row + 64 + j];
        float gg = xg[row + 128 + j];
        float go = xg[row + 192 + j];
        const float* hrow = h_sm + sl * 64;
        #pragma unroll 8
        for (int k = 0; k < 64; k++) {
            float hk = hrow[k];
            float4 w = w4[k * 64 + j];
            gi += hk * w.x; gf += hk * w.y; gg += hk * w.z; go += hk * w.w;
        }
        c = sigm(gf) * c + sigm(gi) * tanhf(gg);
        h = sigm(go) * tanhf(c);
        __syncthreads();
        h_sm[sl * 64 + j] = h;
        __syncthreads();
    }
    hfinal[(size_t)seq * 64 + j] = h;
}

// ---------------- head: fc1 + relu + fc2 + softmax ----------------
__global__ void head_kernel(const float* __restrict__ hfinal,
                            const float* __restrict__ fc1_w, const float* __restrict__ fc1_b,
                            const float* __restrict__ fc2_w, const float* __restrict__ fc2_b,
                            float* __restrict__ out) {
    __shared__ float h[64];
    __shared__ float f1[128];
    __shared__ float logits[3];
    int s = blockIdx.x, tid = threadIdx.x;
    if (tid < 64) h[tid] = hfinal[(size_t)s * 64 + tid];
    __syncthreads();
    float acc = fc1_b[tid];
    #pragma unroll 8
    for (int k = 0; k < 64; k++) acc += h[k] * fc1_w[(size_t)tid * 64 + k];
    f1[tid] = fmaxf(acc, 0.f);
    __syncthreads();
    if (tid < 3) {
        float l = fc2_b[tid];
        #pragma unroll 8
        for (int k = 0; k < 128; k++) l += f1[k] * fc2_w[(size_t)tid * 128 + k];
        logits[tid] = l;
    }
    __syncthreads();
    if (tid == 0) {
        float m = fmaxf(logits[0], fmaxf(logits[1], logits[2]));
        float e0 = expf(logits[0] - m), e1 = expf(logits[1] - m), e2 = expf(logits[2] - m);
        float inv = 1.0f / (e0 + e1 + e2);
        out[(size_t)s * 3 + 0] = e0 * inv;
        out[(size_t)s * 3 + 1] = e1 * inv;
        out[(size_t)s * 3 + 2] = e2 * inv;
    }
}

// ---------------- host launcher ----------------
static void* sym_addr(const void* sym) {
    void* p = nullptr;
    cudaGetSymbolAddress(&p, sym);
    return p;
}

extern "C" void kernel_launch(void* const* d_in, const int* in_sizes, int n_in,
                              void* d_out, int out_size) {
    const float* x        = (const float*)d_in[0];
    const float* ea       = (const float*)d_in[1];
    const float* conv1_w  = (const float*)d_in[2];
    const float* conv1_b  = (const float*)d_in[3];
    const float* conv2_w  = (const float*)d_in[4];
    const float* conv2_b  = (const float*)d_in[5];
    const float* w_ih     = (const float*)d_in[6];
    const float* w_hh     = (const float*)d_in[7];
    const float* b_ih     = (const float*)d_in[8];
    const float* b_hh     = (const float*)d_in[9];
    const float* fc1_w    = (const float*)d_in[10];
    const float* fc1_b    = (const float*)d_in[11];
    const float* fc2_w    = (const float*)d_in[12];
    const float* fc2_b    = (const float*)d_in[13];
    const int*   ei       = (const int*)d_in[14];
    float* out = (float*)d_out;

    float* h1pre = (float*)sym_addr(g_h1pre);
    float* h1    = (float*)sym_addr(g_h1);
    float* h2pre = (float*)sym_addr(g_h2pre);
    float* h2    = (float*)sym_addr(g_h2);
    float* xg    = (float*)sym_addr(g_xg);
    float* hfin  = (float*)sym_addr(g_hfin);

    cudaFuncSetAttribute(lstm_kernel, cudaFuncAttributeMaxDynamicSharedMemorySize, 66560);

    // stats + graph structure
    init_kernel<<<(NTOT + 255) / 256, 256>>>();
    col_stats_kernel<<<200, 256>>>(x);
    stats_finalize_kernel<<<1, 64>>>();
    edge_pass1_kernel<<<ETOT / 256, 256>>>(ei, ea);
    scan1_kernel<<<NTOT / 1024, 1024>>>();
    scan2_kernel<<<1, 32>>>();
    scan3_kernel<<<(NTOT + 255) / 256, 256>>>();
    edge_scatter_kernel<<<ETOT / 256, 256>>>(ei, ea);

    // conv1: h1 = relu(agg(norm(x) @ W1) + b1)
    gemm_kernel<true, false><<<dim3(NTOT / 64, 2), 256>>>(x, conv1_w, nullptr, nullptr, h1pre, 64, L1F);
    agg_kernel<L1F><<<NTOT / 8, 256>>>(h1pre, conv1_b, h1);

    // conv2: h2 = relu(agg(h1 @ W2) + b2)
    gemm_kernel<false, false><<<dim3(NTOT / 64, 1), 256>>>(h1, conv2_w, nullptr, nullptr, h2pre, L1F, L2F);
    agg_kernel<L2F><<<NTOT / 8, 256>>>(h2pre, conv2_b, h2);

    // LSTM input projection: xg = h2 @ w_ih^T + (b_ih + b_hh)
    gemm_kernel<false, true><<<dim3(NTOT / 64, 4), 256>>>(h2, w_ih, b_ih, b_hh, xg, L2F, GATES);

    // recurrence
    lstm_kernel<<<NSEQ / 4, 256, 66560>>>(xg, w_hh, hfin);

    // head
    head_kernel<<<NSEQ, 128>>>(hfin, fc1_w, fc1_b, fc2_w, fc2_b, out);
}

// round 3
// speedup vs baseline: 1.1785x; 1.1785x over previous
#include <cuda_runtime.h>
#include <math.h>

// ---------------- problem constants ----------------
#define NTOT   102400          // B*T*NODES
#define ETOT   1638400         // edges
#define BATCH  8
#define TSTEPS 32
#define NODES  400
#define NSEQ   (BATCH*NODES)   // 3200
#define D_IN   64
#define L1F    96
#define L2F    64
#define GATES  256             // 4*64
#define FC1F   128
#define FC2F   3

// ---------------- device scratch (static: allowed) ----------------
__device__ float g_colsum[64];
__device__ float g_colsumsq[64];
__device__ float g_mean[64];
__device__ float g_rstd[64];
__device__ int   g_counts[NTOT];
__device__ int   g_rowptr[NTOT + 1];
__device__ int   g_cursor[NTOT];
__device__ int   g_bsums[128];
__device__ float g_deg[NTOT];
__device__ float g_dis[NTOT];
__device__ int   g_csrsrc[ETOT];
__device__ float g_csrw[ETOT];
__device__ float g_h1pre[(size_t)NTOT * L1F];
__device__ float g_h1   [(size_t)NTOT * L1F];
__device__ float g_h2pre[(size_t)NTOT * L2F];
__device__ float g_h2   [(size_t)NTOT * L2F];
__device__ float g_xg   [(size_t)NTOT * GATES];
__device__ float g_hfin [(size_t)NSEQ * L2F];

// ---------------- init ----------------
__global__ void init_kernel() {
    int gid = blockIdx.x * blockDim.x + threadIdx.x;
    if (gid < NTOT) { g_counts[gid] = 0; g_deg[gid] = 1.0f; }
    if (gid < 64)   { g_colsum[gid] = 0.f; g_colsumsq[gid] = 0.f; }
}

// ---------------- column stats (mean/std, ddof=1) ----------------
__global__ void col_stats_kernel(const float* __restrict__ x) {
    __shared__ float ssum[256], ssq[256];
    int c  = threadIdx.x & 63;
    int rr = threadIdx.x >> 6;
    float s = 0.f, q = 0.f;
    for (int row = blockIdx.x * 4 + rr; row < NTOT; row += gridDim.x * 4) {
        float v = x[(size_t)row * 64 + c];
        s += v; q += v * v;
    }
    ssum[threadIdx.x] = s; ssq[threadIdx.x] = q;
    __syncthreads();
    if (threadIdx.x < 64) {
        float S = ssum[threadIdx.x] + ssum[threadIdx.x + 64] + ssum[threadIdx.x + 128] + ssum[threadIdx.x + 192];
        float Q = ssq [threadIdx.x] + ssq [threadIdx.x + 64] + ssq [threadIdx.x + 128] + ssq [threadIdx.x + 192];
        atomicAdd(&g_colsum[threadIdx.x], S);
        atomicAdd(&g_colsumsq[threadIdx.x], Q);
    }
}

__global__ void stats_finalize_kernel() {
    int c = threadIdx.x;
    if (c < 64) {
        float n = (float)NTOT;
        float mean = g_colsum[c] / n;
        float var  = (g_colsumsq[c] - n * mean * mean) / (n - 1.0f);
        g_mean[c] = mean;
        g_rstd[c] = rsqrtf(var);
    }
}

// ---------------- edge pass 1: histogram + weighted degree ----------------
__global__ void edge_pass1_kernel(const int* __restrict__ ei, const float* __restrict__ ea) {
    int e = blockIdx.x * blockDim.x + threadIdx.x;
    if (e >= ETOT) return;
    int dst = ei[ETOT + e];
    float w = fabsf(ea[2 * e]);
    atomicAdd(&g_counts[dst], 1);
    atomicAdd(&g_deg[dst], w);
}

// ---------------- scan (exclusive) over counts ----------------
__global__ void scan1_kernel() {
    __shared__ int tmp[1024];
    int gid = blockIdx.x * 1024 + threadIdx.x;
    int v = g_counts[gid];
    tmp[threadIdx.x] = v;
    __syncthreads();
    int val = v;
    for (int off = 1; off < 1024; off <<= 1) {
        int add = (threadIdx.x >= off) ? tmp[threadIdx.x - off] : 0;
        __syncthreads();
        val += add;
        tmp[threadIdx.x] = val;
        __syncthreads();
    }
    g_rowptr[gid] = val - v;           // exclusive, local to block
    if (threadIdx.x == 1023) g_bsums[blockIdx.x] = val;
}

__global__ void scan2_kernel() {
    __shared__ int tmp[128];
    int t = threadIdx.x;
    int v = (t < NTOT / 1024) ? g_bsums[t] : 0;
    tmp[t] = v;
    __syncthreads();
    int val = v;
    for (int off = 1; off < 128; off <<= 1) {
        int add = (t >= off) ? tmp[t - off] : 0;
        __syncthreads();
        val += add;
        tmp[t] = val;
        __syncthreads();
    }
    if (t < NTOT / 1024) g_bsums[t] = val - v;   // exclusive
}

__global__ void scan3_kernel() {
    int gid = blockIdx.x * blockDim.x + threadIdx.x;
    if (gid >= NTOT) return;
    int rp = g_rowptr[gid] + g_bsums[gid >> 10];
    g_rowptr[gid] = rp;
    g_cursor[gid] = rp;
    g_dis[gid] = rsqrtf(g_deg[gid]);   // deg >= 1 always (self loop weight 1)
    if (gid == 0) g_rowptr[NTOT] = ETOT;
}

// ---------------- edge pass 2: scatter into CSR ----------------
__global__ void edge_scatter_kernel(const int* __restrict__ ei, const float* __restrict__ ea) {
    int e = blockIdx.x * blockDim.x + threadIdx.x;
    if (e >= ETOT) return;
    int dst = ei[ETOT + e];
    int src = ei[e];
    float w = fabsf(ea[2 * e]);
    int pos = atomicAdd(&g_cursor[dst], 1);
    g_csrsrc[pos] = src;
    g_csrw[pos] = w;
}

// ---------------- tiled SGEMM: C[M,Nout] = A[M,K] * B + bias (+bias2) ----------------
// BM=64, BN=64, BK=16, 256 threads, thread tile 4x4, float4 smem paths
template<bool NORM, bool TRANSB>
__global__ void gemm_kernel(const float* __restrict__ A, const float* __restrict__ Bm,
                            const float* __restrict__ bias, const float* __restrict__ bias2,
                            float* __restrict__ C, int K, int Nout) {
    __shared__ __align__(16) float As[16][68];
    __shared__ __align__(16) float Bs[16][68];
    int tid = threadIdx.x;
    int tx = tid & 15, ty = tid >> 4;
    int m0 = blockIdx.x * 64, n0 = blockIdx.y * 64;
    float acc[4][4] = {};
    for (int k0 = 0; k0 < K; k0 += 16) {
        // A tile: 64 rows x 16 cols, one float4 per thread
        {
            int r = tid >> 2, c4 = (tid & 3) * 4;
            float4 a = *(const float4*)(A + (size_t)(m0 + r) * K + k0 + c4);
            if (NORM) {
                a.x = (a.x - g_mean[k0 + c4])     * g_rstd[k0 + c4];
                a.y = (a.y - g_mean[k0 + c4 + 1]) * g_rstd[k0 + c4 + 1];
                a.z = (a.z - g_mean[k0 + c4 + 2]) * g_rstd[k0 + c4 + 2];
                a.w = (a.w - g_mean[k0 + c4 + 3]) * g_rstd[k0 + c4 + 3];
            }
            As[c4][r] = a.x; As[c4 + 1][r] = a.y; As[c4 + 2][r] = a.z; As[c4 + 3][r] = a.w;
        }
        // B tile: 16 rows (k) x 64 cols (n)
        if (!TRANSB) {
            int r = tid >> 4, c = (tid & 15) * 4;
            int n = n0 + c, kk = k0 + r;
            float4 b = make_float4(0.f, 0.f, 0.f, 0.f);
            if (n + 3 < Nout) {
                b = *(const float4*)(Bm + (size_t)kk * Nout + n);
            } else {
                if (n     < Nout) b.x = Bm[(size_t)kk * Nout + n];
                if (n + 1 < Nout) b.y = Bm[(size_t)kk * Nout + n + 1];
                if (n + 2 < Nout) b.z = Bm[(size_t)kk * Nout + n + 2];
                if (n + 3 < Nout) b.w = Bm[(size_t)kk * Nout + n + 3];
            }
            Bs[r][c] = b.x; Bs[r][c + 1] = b.y; Bs[r][c + 2] = b.z; Bs[r][c + 3] = b.w;
        } else {
            int c = tid & 63, r4 = (tid >> 6) * 4;      // n0+c always < Nout (Nout=256)
            float4 b = *(const float4*)(Bm + (size_t)(n0 + c) * K + k0 + r4);
            Bs[r4][c] = b.x; Bs[r4 + 1][c] = b.y; Bs[r4 + 2][c] = b.z; Bs[r4 + 3][c] = b.w;
        }
        __syncthreads();
        #pragma unroll
        for (int kk = 0; kk < 16; kk++) {
            float4 a = *(const float4*)&As[kk][ty * 4];
            float4 b = *(const float4*)&Bs[kk][tx * 4];
            acc[0][0] += a.x * b.x; acc[0][1] += a.x * b.y; acc[0][2] += a.x * b.z; acc[0][3] += a.x * b.w;
            acc[1][0] += a.y * b.x; acc[1][1] += a.y * b.y; acc[1][2] += a.y * b.z; acc[1][3] += a.y * b.w;
            acc[2][0] += a.z * b.x; acc[2][1] += a.z * b.y; acc[2][2] += a.z * b.z; acc[2][3] += a.z * b.w;
            acc[3][0] += a.w * b.x; acc[3][1] += a.w * b.y; acc[3][2] += a.w * b.z; acc[3][3] += a.w * b.w;
        }
        __syncthreads();
    }
    #pragma unroll
    for (int i = 0; i < 4; i++) {
        int m = m0 + ty * 4 + i;
        int n = n0 + tx * 4;
        float4 v;
        v.x = acc[i][0]; v.y = acc[i][1]; v.z = acc[i][2]; v.w = acc[i][3];
        if (bias)  { v.x += bias[n];  v.y += bias[n + 1];  v.z += bias[n + 2];  v.w += bias[n + 3]; }
        if (bias2) { v.x += bias2[n]; v.y += bias2[n + 1]; v.z += bias2[n + 2]; v.w += bias2[n + 3]; }
        if (n + 3 < Nout) {
            *(float4*)(C + (size_t)m * Nout + n) = v;
        } else {
            if (n     < Nout) C[(size_t)m * Nout + n]     = v.x;
            if (n + 1 < Nout) C[(size_t)m * Nout + n + 1] = v.y;
            if (n + 2 < Nout) C[(size_t)m * Nout + n + 2] = v.z;
            if (n + 3 < Nout) C[(size_t)m * Nout + n + 3] = v.w;
        }
    }
}

// ---------------- GCN aggregation: one warp per destination node, 4-edge unroll ----------------
template<int F>
__global__ void agg_kernel(const float* __restrict__ hpre, const float* __restrict__ bias,
                           float* __restrict__ out) {
    int warpId = (blockIdx.x * blockDim.x + threadIdx.x) >> 5;
    int lane = threadIdx.x & 31;
    if (warpId >= NTOT) return;
    const int R = F / 32;
    int i = warpId;
    int beg = g_rowptr[i], end = g_rowptr[i + 1];
    float di = g_dis[i];
    float acc[R];
    #pragma unroll
    for (int r = 0; r < R; r++) acc[r] = 0.f;

    for (int e0 = beg; e0 < end; e0 += 32) {
        int cnt = min(32, end - e0);
        int s_l = i; float w_l = 0.f;               // safe defaults: weight 0
        if (lane < cnt) {
            s_l = g_csrsrc[e0 + lane];
            w_l = g_csrw[e0 + lane] * g_dis[s_l];
        }
        for (int j = 0; j < cnt; j += 4) {
            int   s0 = __shfl_sync(0xffffffffu, s_l, j);
            int   s1 = __shfl_sync(0xffffffffu, s_l, j + 1);
            int   s2 = __shfl_sync(0xffffffffu, s_l, j + 2);
            int   s3 = __shfl_sync(0xffffffffu, s_l, j + 3);
            float w0 = __shfl_sync(0xffffffffu, w_l, j);
            float w1 = __shfl_sync(0xffffffffu, w_l, j + 1);
            float w2 = __shfl_sync(0xffffffffu, w_l, j + 2);
            float w3 = __shfl_sync(0xffffffffu, w_l, j + 3);
            const float* r0 = hpre + (size_t)s0 * F + lane;
            const float* r1 = hpre + (size_t)s1 * F + lane;
            const float* r2 = hpre + (size_t)s2 * F + lane;
            const float* r3 = hpre + (size_t)s3 * F + lane;
            float v0[R], v1[R], v2[R], v3[R];
            #pragma unroll
            for (int r = 0; r < R; r++) { v0[r] = r0[32 * r]; v1[r] = r1[32 * r]; v2[r] = r2[32 * r]; v3[r] = r3[32 * r]; }
            #pragma unroll
            for (int r = 0; r < R; r++)
                acc[r] += v0[r] * w0 + v1[r] * w1 + v2[r] * w2 + v3[r] * w3;
        }
    }
    const float* self = hpre + (size_t)i * F;
    #pragma unroll
    for (int r = 0; r < R; r++) {
        float v = acc[r] * di + self[lane + 32 * r] * di * di + bias[lane + 32 * r];
        out[(size_t)i * F + lane + 32 * r] = fmaxf(v, 0.f);
    }
}

// ---------------- LSTM: register-resident weights ----------------
// 2 sequences per block, 256 threads. Thread t = (unit j = t&63, k-chunk kc = t>>6).
// Each thread holds w_hh[gate][j][k0..k0+15] in 64 registers, computes partial gates
// for BOTH seqs; partials reduced via smem float4; threads t<128 do activations.
__device__ __forceinline__ float sigm(float x) { return 1.0f / (1.0f + expf(-x)); }

__global__ __launch_bounds__(256) void lstm_kernel(const float* __restrict__ xg,
                                                   const float* __restrict__ w_hh,
                                                   float* __restrict__ hfinal) {
    __shared__ float  h_sm[2][64];
    __shared__ __align__(16) float4 p_sm[2][4][64];
    int t = threadIdx.x;
    int j = t & 63, kc = t >> 6;
    int k0 = kc * 16;

    float wI[16], wF[16], wG[16], wO[16];
    #pragma unroll
    for (int kk = 0; kk < 16; kk++) {
        wI[kk] = w_hh[(size_t)(      j) * 64 + k0 + kk];
        wF[kk] = w_hh[(size_t)( 64 + j) * 64 + k0 + kk];
        wG[kk] = w_hh[(size_t)(128 + j) * 64 + k0 + kk];
        wO[kk] = w_hh[(size_t)(192 + j) * 64 + k0 + kk];
    }
    int seq0 = blockIdx.x * 2;
    int bA = seq0 / NODES,       nA = seq0 % NODES;
    int bB = (seq0 + 1) / NODES, nB = (seq0 + 1) % NODES;

    float c_state = 0.f;          // valid on threads t<128 (reducer for seq kc, unit j)
    if (t < 128) h_sm[kc][j] = 0.f;
    __syncthreads();

    for (int step = 0; step < TSTEPS; step++) {
        float ai = 0.f, af = 0.f, ag = 0.f, ao = 0.f;   // seq0 partials
        float bi = 0.f, bf = 0.f, bg = 0.f, bo = 0.f;   // seq1 partials
        #pragma unroll
        for (int kk = 0; kk < 16; kk++) {
            float h0 = h_sm[0][k0 + kk];
            float h1 = h_sm[1][k0 + kk];
            ai += h0 * wI[kk]; af += h0 * wF[kk]; ag += h0 * wG[kk]; ao += h0 * wO[kk];
            bi += h1 * wI[kk]; bf += h1 * wF[kk]; bg += h1 * wG[kk]; bo += h1 * wO[kk];
        }
        p_sm[0][kc][j] = make_float4(ai, af, ag, ao);
        p_sm[1][kc][j] = make_float4(bi, bf, bg, bo);
        __syncthreads();
        if (t < 128) {
            int s = kc;                                  // 0 or 1
            int bb = s ? bB : bA, nn = s ? nB : nA;
            size_t row = ((size_t)(bb * TSTEPS + step) * NODES + nn) * GATES;
            float4 p = p_sm[s][0][j];
            float4 q = p_sm[s][1][j];
            float4 r = p_sm[s][2][j];
            float4 w = p_sm[s][3][j];
            float gi = p.x + q.x + r.x + w.x + xg[row + j];
            float gf = p.y + q.y + r.y + w.y + xg[row + 64 + j];
            float gg = p.z + q.z + r.z + w.z + xg[row + 128 + j];
            float go = p.w + q.w + r.w + w.w + xg[row + 192 + j];
            c_state = sigm(gf) * c_state + sigm(gi) * tanhf(gg);
            h_sm[s][j] = sigm(go) * tanhf(c_state);
        }
        __syncthreads();
    }
    if (t < 128) hfinal[(size_t)(seq0 + kc) * 64 + j] = h_sm[kc][j];
}

// ---------------- head: fc1 + relu + fc2 + softmax ----------------
__global__ void head_kernel(const float* __restrict__ hfinal,
                            const float* __restrict__ fc1_w, const float* __restrict__ fc1_b,
                            const float* __restrict__ fc2_w, const float* __restrict__ fc2_b,
                            float* __restrict__ out) {
    __shared__ float h[64];
    __shared__ float f1[128];
    __shared__ float logits[3];
    int s = blockIdx.x, tid = threadIdx.x;
    if (tid < 64) h[tid] = hfinal[(size_t)s * 64 + tid];
    __syncthreads();
    float acc = fc1_b[tid];
    #pragma unroll 8
    for (int k = 0; k < 64; k++) acc += h[k] * fc1_w[(size_t)tid * 64 + k];
    f1[tid] = fmaxf(acc, 0.f);
    __syncthreads();
    if (tid < 3) {
        float l = fc2_b[tid];
        #pragma unroll 8
        for (int k = 0; k < 128; k++) l += f1[k] * fc2_w[(size_t)tid * 128 + k];
        logits[tid] = l;
    }
    __syncthreads();
    if (tid == 0) {
        float m = fmaxf(logits[0], fmaxf(logits[1], logits[2]));
        float e0 = expf(logits[0] - m), e1 = expf(logits[1] - m), e2 = expf(logits[2] - m);
        float inv = 1.0f / (e0 + e1 + e2);
        out[(size_t)s * 3 + 0] = e0 * inv;
        out[(size_t)s * 3 + 1] = e1 * inv;
        out[(size_t)s * 3 + 2] = e2 * inv;
    }
}

// ---------------- host launcher ----------------
static void* sym_addr(const void* sym) {
    void* p = nullptr;
    cudaGetSymbolAddress(&p, sym);
    return p;
}

extern "C" void kernel_launch(void* const* d_in, const int* in_sizes, int n_in,
                              void* d_out, int out_size) {
    const float* x        = (const float*)d_in[0];
    const float* ea       = (const float*)d_in[1];
    const float* conv1_w  = (const float*)d_in[2];
    const float* conv1_b  = (const float*)d_in[3];
    const float* conv2_w  = (const float*)d_in[4];
    const float* conv2_b  = (const float*)d_in[5];
    const float* w_ih     = (const float*)d_in[6];
    const float* w_hh     = (const float*)d_in[7];
    const float* b_ih     = (const float*)d_in[8];
    const float* b_hh     = (const float*)d_in[9];
    const float* fc1_w    = (const float*)d_in[10];
    const float* fc1_b    = (const float*)d_in[11];
    const float* fc2_w    = (const float*)d_in[12];
    const float* fc2_b    = (const float*)d_in[13];
    const int*   ei       = (const int*)d_in[14];
    float* out = (float*)d_out;

    float* h1pre = (float*)sym_addr(g_h1pre);
    float* h1    = (float*)sym_addr(g_h1);
    float* h2pre = (float*)sym_addr(g_h2pre);
    float* h2    = (float*)sym_addr(g_h2);
    float* xg    = (float*)sym_addr(g_xg);
    float* hfin  = (float*)sym_addr(g_hfin);

    // stats + graph structure
    init_kernel<<<(NTOT + 255) / 256, 256>>>();
    col_stats_kernel<<<200, 256>>>(x);
    stats_finalize_kernel<<<1, 64>>>();
    edge_pass1_kernel<<<ETOT / 256, 256>>>(ei, ea);
    scan1_kernel<<<NTOT / 1024, 1024>>>();
    scan2_kernel<<<1, 128>>>();
    scan3_kernel<<<(NTOT + 255) / 256, 256>>>();
    edge_scatter_kernel<<<ETOT / 256, 256>>>(ei, ea);

    // conv1: h1 = relu(agg(norm(x) @ W1) + b1)
    gemm_kernel<true, false><<<dim3(NTOT / 64, 2), 256>>>(x, conv1_w, nullptr, nullptr, h1pre, 64, L1F);
    agg_kernel<L1F><<<NTOT / 8, 256>>>(h1pre, conv1_b, h1);

    // conv2: h2 = relu(agg(h1 @ W2) + b2)
    gemm_kernel<false, false><<<dim3(NTOT / 64, 1), 256>>>(h1, conv2_w, nullptr, nullptr, h2pre, L1F, L2F);
    agg_kernel<L2F><<<NTOT / 8, 256>>>(h2pre, conv2_b, h2);

    // LSTM input projection: xg = h2 @ w_ih^T + (b_ih + b_hh)
    gemm_kernel<false, true><<<dim3(NTOT / 64, 4), 256>>>(h2, w_ih, b_ih, b_hh, xg, L2F, GATES);

    // recurrence (register-resident weights, 2 seqs/block)
    lstm_kernel<<<NSEQ / 2, 256>>>(xg, w_hh, hfin);

    // head
    head_kernel<<<NSEQ, 128>>>(hfin, fc1_w, fc1_b, fc2_w, fc2_b, out);
}

// round 4
// speedup vs baseline: 1.1864x; 1.0067x over previous
#include <cuda_runtime.h>
#include <math.h>

// ---------------- problem constants ----------------
#define NTOT   102400          // B*T*NODES
#define ETOT   1638400         // edges
#define BATCH  8
#define TSTEPS 32
#define NODES  400
#define NSEQ   (BATCH*NODES)   // 3200
#define D_IN   64
#define L1F    96
#define L2F    64
#define GATES  256             // 4*64
#define FC1F   128
#define FC2F   3

// ---------------- device scratch (static: allowed) ----------------
__device__ float g_colsum[64];
__device__ float g_colsumsq[64];
__device__ float g_mean[64];
__device__ float g_rstd[64];
__device__ int   g_counts[NTOT];
__device__ int   g_rowptr[NTOT + 1];
__device__ int   g_cursor[NTOT];
__device__ int   g_bsums[128];
__device__ float g_deg[NTOT];
__device__ float g_dis[NTOT];
__device__ int   g_csrsrc[ETOT];
__device__ float g_csrw[ETOT];
__device__ float g_h1pre[(size_t)NTOT * L1F];
__device__ float g_h1   [(size_t)NTOT * L1F];
__device__ float g_h2pre[(size_t)NTOT * L2F];
__device__ float g_h2   [(size_t)NTOT * L2F];
__device__ float g_xg   [(size_t)NTOT * GATES];
__device__ float g_hfin [(size_t)NSEQ * L2F];

// ---------------- init ----------------
__global__ void init_kernel() {
    int gid = blockIdx.x * blockDim.x + threadIdx.x;
    if (gid < NTOT) { g_counts[gid] = 0; g_deg[gid] = 1.0f; }
    if (gid < 64)   { g_colsum[gid] = 0.f; g_colsumsq[gid] = 0.f; }
}

// ---------------- column stats (mean/std, ddof=1) ----------------
__global__ void col_stats_kernel(const float* __restrict__ x) {
    __shared__ float ssum[256], ssq[256];
    int c  = threadIdx.x & 63;
    int rr = threadIdx.x >> 6;
    float s = 0.f, q = 0.f;
    for (int row = blockIdx.x * 4 + rr; row < NTOT; row += gridDim.x * 4) {
        float v = x[(size_t)row * 64 + c];
        s += v; q += v * v;
    }
    ssum[threadIdx.x] = s; ssq[threadIdx.x] = q;
    __syncthreads();
    if (threadIdx.x < 64) {
        float S = ssum[threadIdx.x] + ssum[threadIdx.x + 64] + ssum[threadIdx.x + 128] + ssum[threadIdx.x + 192];
        float Q = ssq [threadIdx.x] + ssq [threadIdx.x + 64] + ssq [threadIdx.x + 128] + ssq [threadIdx.x + 192];
        atomicAdd(&g_colsum[threadIdx.x], S);
        atomicAdd(&g_colsumsq[threadIdx.x], Q);
    }
}

__global__ void stats_finalize_kernel() {
    int c = threadIdx.x;
    if (c < 64) {
        float n = (float)NTOT;
        float mean = g_colsum[c] / n;
        float var  = (g_colsumsq[c] - n * mean * mean) / (n - 1.0f);
        g_mean[c] = mean;
        g_rstd[c] = rsqrtf(var);
    }
}

// ---------------- edge pass 1: histogram + weighted degree ----------------
__global__ void edge_pass1_kernel(const int* __restrict__ ei, const float* __restrict__ ea) {
    int e = blockIdx.x * blockDim.x + threadIdx.x;
    if (e >= ETOT) return;
    int dst = ei[ETOT + e];
    float w = fabsf(ea[2 * e]);
    atomicAdd(&g_counts[dst], 1);
    atomicAdd(&g_deg[dst], w);
}

// ---------------- scan (exclusive) over counts ----------------
__global__ void scan1_kernel() {
    __shared__ int tmp[1024];
    int gid = blockIdx.x * 1024 + threadIdx.x;
    int v = g_counts[gid];
    tmp[threadIdx.x] = v;
    __syncthreads();
    int val = v;
    for (int off = 1; off < 1024; off <<= 1) {
        int add = (threadIdx.x >= off) ? tmp[threadIdx.x - off] : 0;
        __syncthreads();
        val += add;
        tmp[threadIdx.x] = val;
        __syncthreads();
    }
    g_rowptr[gid] = val - v;           // exclusive, local to block
    if (threadIdx.x == 1023) g_bsums[blockIdx.x] = val;
}

__global__ void scan2_kernel() {
    __shared__ int tmp[128];
    int t = threadIdx.x;
    int v = (t < NTOT / 1024) ? g_bsums[t] : 0;
    tmp[t] = v;
    __syncthreads();
    int val = v;
    for (int off = 1; off < 128; off <<= 1) {
        int add = (t >= off) ? tmp[t - off] : 0;
        __syncthreads();
        val += add;
        tmp[t] = val;
        __syncthreads();
    }
    if (t < NTOT / 1024) g_bsums[t] = val - v;   // exclusive
}

__global__ void scan3_kernel() {
    int gid = blockIdx.x * blockDim.x + threadIdx.x;
    if (gid >= NTOT) return;
    int rp = g_rowptr[gid] + g_bsums[gid >> 10];
    g_rowptr[gid] = rp;
    g_cursor[gid] = rp;
    g_dis[gid] = rsqrtf(g_deg[gid]);   // deg >= 1 always (self loop weight 1)
    if (gid == 0) g_rowptr[NTOT] = ETOT;
}

// ---------------- edge pass 2: scatter into CSR ----------------
__global__ void edge_scatter_kernel(const int* __restrict__ ei, const float* __restrict__ ea) {
    int e = blockIdx.x * blockDim.x + threadIdx.x;
    if (e >= ETOT) return;
    int dst = ei[ETOT + e];
    int src = ei[e];
    float w = fabsf(ea[2 * e]);
    int pos = atomicAdd(&g_cursor[dst], 1);
    g_csrsrc[pos] = src;
    g_csrw[pos] = w;
}

// ---------------- tiled SGEMM: C[M,Nout] = A[M,K] * B + bias (+bias2) ----------------
// BM=64, BN=64, BK=16, 256 threads, thread tile 4x4, float4 smem paths
template<bool NORM, bool TRANSB>
__global__ void gemm_kernel(const float* __restrict__ A, const float* __restrict__ Bm,
                            const float* __restrict__ bias, const float* __restrict__ bias2,
                            float* __restrict__ C, int K, int Nout) {
    __shared__ __align__(16) float As[16][68];
    __shared__ __align__(16) float Bs[16][68];
    int tid = threadIdx.x;
    int tx = tid & 15, ty = tid >> 4;
    int m0 = blockIdx.x * 64, n0 = blockIdx.y * 64;
    float acc[4][4] = {};
    for (int k0 = 0; k0 < K; k0 += 16) {
        // A tile: 64 rows x 16 cols, one float4 per thread
        {
            int r = tid >> 2, c4 = (tid & 3) * 4;
            float4 a = *(const float4*)(A + (size_t)(m0 + r) * K + k0 + c4);
            if (NORM) {
                a.x = (a.x - g_mean[k0 + c4])     * g_rstd[k0 + c4];
                a.y = (a.y - g_mean[k0 + c4 + 1]) * g_rstd[k0 + c4 + 1];
                a.z = (a.z - g_mean[k0 + c4 + 2]) * g_rstd[k0 + c4 + 2];
                a.w = (a.w - g_mean[k0 + c4 + 3]) * g_rstd[k0 + c4 + 3];
            }
            As[c4][r] = a.x; As[c4 + 1][r] = a.y; As[c4 + 2][r] = a.z; As[c4 + 3][r] = a.w;
        }
        // B tile: 16 rows (k) x 64 cols (n)
        if (!TRANSB) {
            int r = tid >> 4, c = (tid & 15) * 4;
            int n = n0 + c, kk = k0 + r;
            float4 b = make_float4(0.f, 0.f, 0.f, 0.f);
            if (n + 3 < Nout) {
                b = *(const float4*)(Bm + (size_t)kk * Nout + n);
            } else {
                if (n     < Nout) b.x = Bm[(size_t)kk * Nout + n];
                if (n + 1 < Nout) b.y = Bm[(size_t)kk * Nout + n + 1];
                if (n + 2 < Nout) b.z = Bm[(size_t)kk * Nout + n + 2];
                if (n + 3 < Nout) b.w = Bm[(size_t)kk * Nout + n + 3];
            }
            Bs[r][c] = b.x; Bs[r][c + 1] = b.y; Bs[r][c + 2] = b.z; Bs[r][c + 3] = b.w;
        } else {
            int c = tid & 63, r4 = (tid >> 6) * 4;      // n0+c always < Nout (Nout=256)
            float4 b = *(const float4*)(Bm + (size_t)(n0 + c) * K + k0 + r4);
            Bs[r4][c] = b.x; Bs[r4 + 1][c] = b.y; Bs[r4 + 2][c] = b.z; Bs[r4 + 3][c] = b.w;
        }
        __syncthreads();
        #pragma unroll
        for (int kk = 0; kk < 16; kk++) {
            float4 a = *(const float4*)&As[kk][ty * 4];
            float4 b = *(const float4*)&Bs[kk][tx * 4];
            acc[0][0] += a.x * b.x; acc[0][1] += a.x * b.y; acc[0][2] += a.x * b.z; acc[0][3] += a.x * b.w;
            acc[1][0] += a.y * b.x; acc[1][1] += a.y * b.y; acc[1][2] += a.y * b.z; acc[1][3] += a.y * b.w;
            acc[2][0] += a.z * b.x; acc[2][1] += a.z * b.y; acc[2][2] += a.z * b.z; acc[2][3] += a.z * b.w;
            acc[3][0] += a.w * b.x; acc[3][1] += a.w * b.y; acc[3][2] += a.w * b.z; acc[3][3] += a.w * b.w;
        }
        __syncthreads();
    }
    #pragma unroll
    for (int i = 0; i < 4; i++) {
        int m = m0 + ty * 4 + i;
        int n = n0 + tx * 4;
        float4 v;
        v.x = acc[i][0]; v.y = acc[i][1]; v.z = acc[i][2]; v.w = acc[i][3];
        if (bias)  { v.x += bias[n];  v.y += bias[n + 1];  v.z += bias[n + 2];  v.w += bias[n + 3]; }
        if (bias2) { v.x += bias2[n]; v.y += bias2[n + 1]; v.z += bias2[n + 2]; v.w += bias2[n + 3]; }
        if (n + 3 < Nout) {
            *(float4*)(C + (size_t)m * Nout + n) = v;
        } else {
            if (n     < Nout) C[(size_t)m * Nout + n]     = v.x;
            if (n + 1 < Nout) C[(size_t)m * Nout + n + 1] = v.y;
            if (n + 2 < Nout) C[(size_t)m * Nout + n + 2] = v.z;
            if (n + 3 < Nout) C[(size_t)m * Nout + n + 3] = v.w;
        }
    }
}

// ---------------- GCN aggregation: one warp per destination node, 4-edge unroll ----------------
template<int F>
__global__ void agg_kernel(const float* __restrict__ hpre, const float* __restrict__ bias,
                           float* __restrict__ out) {
    int warpId = (blockIdx.x * blockDim.x + threadIdx.x) >> 5;
    int lane = threadIdx.x & 31;
    if (warpId >= NTOT) return;
    const int R = F / 32;
    int i = warpId;
    int beg = g_rowptr[i], end = g_rowptr[i + 1];
    float di = g_dis[i];
    float acc[R];
    #pragma unroll
    for (int r = 0; r < R; r++) acc[r] = 0.f;

    for (int e0 = beg; e0 < end; e0 += 32) {
        int cnt = min(32, end - e0);
        int s_l = i; float w_l = 0.f;               // safe defaults: weight 0
        if (lane < cnt) {
            s_l = g_csrsrc[e0 + lane];
            w_l = g_csrw[e0 + lane] * g_dis[s_l];
        }
        for (int j = 0; j < cnt; j += 4) {
            int   s0 = __shfl_sync(0xffffffffu, s_l, j);
            int   s1 = __shfl_sync(0xffffffffu, s_l, j + 1);
            int   s2 = __shfl_sync(0xffffffffu, s_l, j + 2);
            int   s3 = __shfl_sync(0xffffffffu, s_l, j + 3);
            float w0 = __shfl_sync(0xffffffffu, w_l, j);
            float w1 = __shfl_sync(0xffffffffu, w_l, j + 1);
            float w2 = __shfl_sync(0xffffffffu, w_l, j + 2);
            float w3 = __shfl_sync(0xffffffffu, w_l, j + 3);
            const float* r0 = hpre + (size_t)s0 * F + lane;
            const float* r1 = hpre + (size_t)s1 * F + lane;
            const float* r2 = hpre + (size_t)s2 * F + lane;
            const float* r3 = hpre + (size_t)s3 * F + lane;
            float v0[R], v1[R], v2[R], v3[R];
            #pragma unroll
            for (int r = 0; r < R; r++) { v0[r] = r0[32 * r]; v1[r] = r1[32 * r]; v2[r] = r2[32 * r]; v3[r] = r3[32 * r]; }
            #pragma unroll
            for (int r = 0; r < R; r++)
                acc[r] += v0[r] * w0 + v1[r] * w1 + v2[r] * w2 + v3[r] * w3;
        }
    }
    const float* self = hpre + (size_t)i * F;
    #pragma unroll
    for (int r = 0; r < R; r++) {
        float v = acc[r] * di + self[lane + 32 * r] * di * di + bias[lane + 32 * r];
        out[(size_t)i * F + lane + 32 * r] = fmaxf(v, 0.f);
    }
}

// ---------------- LSTM: register-resident weights ----------------
// 2 sequences per block, 256 threads. Thread t = (unit j = t&63, k-chunk kc = t>>6).
// Each thread holds w_hh[gate][j][k0..k0+15] in 64 registers, computes partial gates
// for BOTH seqs; partials reduced via smem float4; threads t<128 do activations.
__device__ __forceinline__ float sigm(float x) { return 1.0f / (1.0f + expf(-x)); }

__global__ __launch_bounds__(256) void lstm_kernel(const float* __restrict__ xg,
                                                   const float* __restrict__ w_hh,
                                                   float* __restrict__ hfinal) {
    __shared__ float  h_sm[2][64];
    __shared__ __align__(16) float4 p_sm[2][4][64];
    int t = threadIdx.x;
    int j = t & 63, kc = t >> 6;
    int k0 = kc * 16;

    float wI[16], wF[16], wG[16], wO[16];
    #pragma unroll
    for (int kk = 0; kk < 16; kk++) {
        wI[kk] = w_hh[(size_t)(      j) * 64 + k0 + kk];
        wF[kk] = w_hh[(size_t)( 64 + j) * 64 + k0 + kk];
        wG[kk] = w_hh[(size_t)(128 + j) * 64 + k0 + kk];
        wO[kk] = w_hh[(size_t)(192 + j) * 64 + k0 + kk];
    }
    int seq0 = blockIdx.x * 2;
    int bA = seq0 / NODES,       nA = seq0 % NODES;
    int bB = (seq0 + 1) / NODES, nB = (seq0 + 1) % NODES;

    float c_state = 0.f;          // valid on threads t<128 (reducer for seq kc, unit j)
    if (t < 128) h_sm[kc][j] = 0.f;
    __syncthreads();

    for (int step = 0; step < TSTEPS; step++) {
        float ai = 0.f, af = 0.f, ag = 0.f, ao = 0.f;   // seq0 partials
        float bi = 0.f, bf = 0.f, bg = 0.f, bo = 0.f;   // seq1 partials
        #pragma unroll
        for (int kk = 0; kk < 16; kk++) {
            float h0 = h_sm[0][k0 + kk];
            float h1 = h_sm[1][k0 + kk];
            ai += h0 * wI[kk]; af += h0 * wF[kk]; ag += h0 * wG[kk]; ao += h0 * wO[kk];
            bi += h1 * wI[kk]; bf += h1 * wF[kk]; bg += h1 * wG[kk]; bo += h1 * wO[kk];
        }
        p_sm[0][kc][j] = make_float4(ai, af, ag, ao);
        p_sm[1][kc][j] = make_float4(bi, bf, bg, bo);
        __syncthreads();
        if (t < 128) {
            int s = kc;                                  // 0 or 1
            int bb = s ? bB : bA, nn = s ? nB : nA;
            size_t row = ((size_t)(bb * TSTEPS + step) * NODES + nn) * GATES;
            float4 p = p_sm[s][0][j];
            float4 q = p_sm[s][1][j];
            float4 r = p_sm[s][2][j];
            float4 w = p_sm[s][3][j];
            float gi = p.x + q.x + r.x + w.x + xg[row + j];
            float gf = p.y + q.y + r.y + w.y + xg[row + 64 + j];
            float gg = p.z + q.z + r.z + w.z + xg[row + 128 + j];
            float go = p.w + q.w + r.w + w.w + xg[row + 192 + j];
            c_state = sigm(gf) * c_state + sigm(gi) * tanhf(gg);
            h_sm[s][j] = sigm(go) * tanhf(c_state);
        }
        __syncthreads();
    }
    if (t < 128) hfinal[(size_t)(seq0 + kc) * 64 + j] = h_sm[kc][j];
}

// ---------------- head: fc1 + relu + fc2 + softmax ----------------
__global__ void head_kernel(const float* __restrict__ hfinal,
                            const float* __restrict__ fc1_w, const float* __restrict__ fc1_b,
                            const float* __restrict__ fc2_w, const float* __restrict__ fc2_b,
                            float* __restrict__ out) {
    __shared__ float h[64];
    __shared__ float f1[128];
    __shared__ float logits[3];
    int s = blockIdx.x, tid = threadIdx.x;
    if (tid < 64) h[tid] = hfinal[(size_t)s * 64 + tid];
    __syncthreads();
    float acc = fc1_b[tid];
    #pragma unroll 8
    for (int k = 0; k < 64; k++) acc += h[k] * fc1_w[(size_t)tid * 64 + k];
    f1[tid] = fmaxf(acc, 0.f);
    __syncthreads();
    if (tid < 3) {
        float l = fc2_b[tid];
        #pragma unroll 8
        for (int k = 0; k < 128; k++) l += f1[k] * fc2_w[(size_t)tid * 128 + k];
        logits[tid] = l;
    }
    __syncthreads();
    if (tid == 0) {
        float m = fmaxf(logits[0], fmaxf(logits[1], logits[2]));
        float e0 = expf(logits[0] - m), e1 = expf(logits[1] - m), e2 = expf(logits[2] - m);
        float inv = 1.0f / (e0 + e1 + e2);
        out[(size_t)s * 3 + 0] = e0 * inv;
        out[(size_t)s * 3 + 1] = e1 * inv;
        out[(size_t)s * 3 + 2] = e2 * inv;
    }
}

// ---------------- host launcher ----------------
static void* sym_addr(const void* sym) {
    void* p = nullptr;
    cudaGetSymbolAddress(&p, sym);
    return p;
}

extern "C" void kernel_launch(void* const* d_in, const int* in_sizes, int n_in,
                              void* d_out, int out_size) {
    const float* x        = (const float*)d_in[0];
    const float* ea       = (const float*)d_in[1];
    const float* conv1_w  = (const float*)d_in[2];
    const float* conv1_b  = (const float*)d_in[3];
    const float* conv2_w  = (const float*)d_in[4];
    const float* conv2_b  = (const float*)d_in[5];
    const float* w_ih     = (const float*)d_in[6];
    const float* w_hh     = (const float*)d_in[7];
    const float* b_ih     = (const float*)d_in[8];
    const float* b_hh     = (const float*)d_in[9];
    const float* fc1_w    = (const float*)d_in[10];
    const float* fc1_b    = (const float*)d_in[11];
    const float* fc2_w    = (const float*)d_in[12];
    const float* fc2_b    = (const float*)d_in[13];
    const int*   ei       = (const int*)d_in[14];
    float* out = (float*)d_out;

    float* h1pre = (float*)sym_addr(g_h1pre);
    float* h1    = (float*)sym_addr(g_h1);
    float* h2pre = (float*)sym_addr(g_h2pre);
    float* h2    = (float*)sym_addr(g_h2);
    float* xg    = (float*)sym_addr(g_xg);
    float* hfin  = (float*)sym_addr(g_hfin);

    // stats + graph structure
    init_kernel<<<(NTOT + 255) / 256, 256>>>();
    col_stats_kernel<<<200, 256>>>(x);
    stats_finalize_kernel<<<1, 64>>>();
    edge_pass1_kernel<<<ETOT / 256, 256>>>(ei, ea);
    scan1_kernel<<<NTOT / 1024, 1024>>>();
    scan2_kernel<<<1, 128>>>();
    scan3_kernel<<<(NTOT + 255) / 256, 256>>>();
    edge_scatter_kernel<<<ETOT / 256, 256>>>(ei, ea);

    // conv1: h1 = relu(agg(norm(x) @ W1) + b1)
    gemm_kernel<true, false><<<dim3(NTOT / 64, 2), 256>>>(x, conv1_w, nullptr, nullptr, h1pre, 64, L1F);
    agg_kernel<L1F><<<NTOT / 8, 256>>>(h1pre, conv1_b, h1);

    // conv2: h2 = relu(agg(h1 @ W2) + b2)
    gemm_kernel<false, false><<<dim3(NTOT / 64, 1), 256>>>(h1, conv2_w, nullptr, nullptr, h2pre, L1F, L2F);
    agg_kernel<L2F><<<NTOT / 8, 256>>>(h2pre, conv2_b, h2);

    // LSTM input projection: xg = h2 @ w_ih^T + (b_ih + b_hh)
    gemm_kernel<false, true><<<dim3(NTOT / 64, 4), 256>>>(h2, w_ih, b_ih, b_hh, xg, L2F, GATES);

    // recurrence (register-resident weights, 2 seqs/block)
    lstm_kernel<<<NSEQ / 2, 256>>>(xg, w_hh, hfin);

    // head
    head_kernel<<<NSEQ, 128>>>(hfin, fc1_w, fc1_b, fc2_w, fc2_b, out);
}